// round 3
// baseline (speedup 1.0000x reference)
#include <cuda_runtime.h>
#include <cuda_bf16.h>
#include <float.h>

#define BATCH 256
#define NQ 1000
#define NC 80
#define TOPK 300
#define THRESH 0.05f

typedef unsigned long long u64;
typedef unsigned int u32;

__device__ u64 g_keys[BATCH * NQ];

// Order-preserving bijection float -> uint32 (monotone increasing)
__device__ __forceinline__ u32 fkey(float f) {
    u32 u = __float_as_uint(f);
    return (u & 0x80000000u) ? ~u : (u | 0x80000000u);
}
__device__ __forceinline__ float ikey(u32 k) {
    u32 u = (k & 0x80000000u) ? (k ^ 0x80000000u) : ~k;
    return __uint_as_float(u);
}

// ---------------------------------------------------------------------------
// Kernel 1: 256 threads / 32 query rows per block. Stage 40KB to smem with
// 10 independent coalesced LDG.128 per thread (MLP=10, all lanes), then each
// warp reduces 4 queries: 20-lane LDS.128 + REDUX.UMAX on monotone bits +
// ballot (lowest lane = lowest class = jax argmax tie-break).
// Key = [fkey(masked_score):32 | (1023-qi):10 | label:7]  -> sorting this key
// reproduces jax top_k (value desc, index asc) order exactly.
// ---------------------------------------------------------------------------
__global__ void __launch_bounds__(256) k_maxarg(const float* __restrict__ logits) {
    __shared__ float4 sm[2560];                     // 32 rows * 20 float4 = 40KB
    int blk = blockIdx.x;                           // 8000 blocks
    const float4* in = reinterpret_cast<const float4*>(logits) + (size_t)blk * 640;
    int t = threadIdx.x;

    #pragma unroll
    for (int u = 0; u < 10; u++)
        sm[u * 256 + t] = in[u * 256 + t];
    __syncthreads();

    int warp = t >> 5, lane = t & 31;
    #pragma unroll
    for (int qq = 0; qq < 4; qq++) {
        int q = warp * 4 + qq;                       // local query 0..31
        float v = -FLT_MAX; int c = 127;
        if (lane < 20) {
            float4 x = sm[q * 20 + lane];
            v = x.x; c = lane * 4;
            if (x.y > v) { v = x.y; c = lane * 4 + 1; }
            if (x.z > v) { v = x.z; c = lane * 4 + 2; }
            if (x.w > v) { v = x.w; c = lane * 4 + 3; }
        }
        u32 fk = fkey(v);
        u32 m  = __reduce_max_sync(0xffffffffu, fk);
        u32 ms = __ballot_sync(0xffffffffu, fk == m);
        int cc = __shfl_sync(0xffffffffu, c, __ffs(ms) - 1);
        if (lane == 0) {
            float vv = ikey(m);
            float s = 1.0f / (1.0f + expf(-vv));
            float masked = (s > THRESH) ? s : -1.0f;
            int gq = blk * 32 + q;
            int qi = gq % NQ;
            g_keys[gq] = ((u64)fkey(masked) << 17)
                       | ((u64)(1023 - qi) << 7)
                       | (u32)cc;
        }
    }
}

// ---------------------------------------------------------------------------
// Kernel 2: one batch per 256-thread block; 4 keys per thread in REGISTERS.
// Bitonic sort of 1024: 45 phases via shfl_xor (no smem), 4 phases local
// register swaps, only 6 phases (j=128,256,512) through smem => 12 barriers
// of 8 warps, ~4 blocks/SM co-resident to hide them.
// ---------------------------------------------------------------------------
__device__ __forceinline__ u64 shfl_xor_u64(u64 v, int m) {
    u32 lo = __shfl_xor_sync(0xffffffffu, (u32)v, m);
    u32 hi = __shfl_xor_sync(0xffffffffu, (u32)(v >> 32), m);
    return ((u64)hi << 32) | lo;
}

__global__ void __launch_bounds__(256) k_topk(const float* __restrict__ boxes,
                                              const float* __restrict__ tsizes,
                                              float* __restrict__ out) {
    __shared__ u64 sm[1024];
    int b = blockIdx.x;
    int t = threadIdx.x;
    int warp = t >> 5, lane = t & 31;

    u64 v[4];
    #pragma unroll
    for (int r = 0; r < 4; r++) {
        int i = (warp << 7) | (r << 5) | lane;
        v[r] = (i < NQ) ? g_keys[b * NQ + i] : 0ULL;   // pads sort below all real keys
    }

    #pragma unroll 1
    for (int k = 2; k <= 1024; k <<= 1) {
        #pragma unroll 1
        for (int j = k >> 1; j > 0; j >>= 1) {
            if (j >= 128) {
                // cross-warp via smem
                #pragma unroll
                for (int r = 0; r < 4; r++)
                    sm[(warp << 7) | (r << 5) | lane] = v[r];
                __syncthreads();
                #pragma unroll
                for (int r = 0; r < 4; r++) {
                    int i = (warp << 7) | (r << 5) | lane;
                    u64 o = sm[i ^ j];
                    bool keepmax = ((i & k) == 0) != ((i & j) != 0);
                    if (keepmax ? (o > v[r]) : (o < v[r])) v[r] = o;
                }
                __syncthreads();
            } else if (j >= 32) {
                // cross-register, same lane
                int jr = j >> 5;                       // 1 or 2
                #pragma unroll
                for (int r = 0; r < 4; r++) {
                    if (r & jr) continue;
                    int r2 = r | jr;
                    int i = (warp << 7) | (r << 5) | lane;
                    bool desc = (i & k) == 0;
                    u64 a = v[r], c2 = v[r2];
                    u64 mx = (a > c2) ? a : c2;
                    u64 mn = (a > c2) ? c2 : a;
                    v[r]  = desc ? mx : mn;
                    v[r2] = desc ? mn : mx;
                }
            } else {
                // intra-warp shuffle
                #pragma unroll
                for (int r = 0; r < 4; r++) {
                    int i = (warp << 7) | (r << 5) | lane;
                    u64 o = shfl_xor_u64(v[r], j);
                    bool keepmax = ((i & k) == 0) != ((i & j) != 0);
                    if (keepmax ? (o > v[r]) : (o < v[r])) v[r] = o;
                }
            }
        }
    }

    // Epilogue straight from registers: elements i<300
    float img_h = tsizes[b * 2 + 0];
    float img_w = tsizes[b * 2 + 1];
    const float4* bx4 = reinterpret_cast<const float4*>(boxes) + (size_t)b * NQ;

    #pragma unroll
    for (int r = 0; r < 4; r++) {
        int i = (warp << 7) | (r << 5) | lane;
        if (i >= TOPK) continue;
        u64 key = v[r];
        float masked = ikey((u32)(key >> 17));
        int label = (int)(key & 127ULL);
        int qi = 1023 - (int)((key >> 7) & 1023ULL);
        bool valid = masked > THRESH;

        float4 bx = bx4[qi];
        float x0 = (bx.x - 0.5f * bx.z) * img_w;
        float y0 = (bx.y - 0.5f * bx.w) * img_h;
        float x1 = (bx.x + 0.5f * bx.z) * img_w;
        float y1 = (bx.y + 0.5f * bx.w) * img_h;

        int o = b * TOPK + i;
        out[o] = valid ? masked : 0.0f;
        out[BATCH * TOPK + o] = valid ? (float)label : -1.0f;
        float* ob = out + 2 * BATCH * TOPK + (size_t)o * 4;
        ob[0] = valid ? x0 : 0.0f;
        ob[1] = valid ? y0 : 0.0f;
        ob[2] = valid ? x1 : 0.0f;
        ob[3] = valid ? y1 : 0.0f;
    }
}

extern "C" void kernel_launch(void* const* d_in, const int* in_sizes, int n_in,
                              void* d_out, int out_size) {
    const float* pred_logits  = (const float*)d_in[0];
    const float* pred_boxes   = (const float*)d_in[1];
    const float* target_sizes = (const float*)d_in[2];
    float* out = (float*)d_out;

    k_maxarg<<<BATCH * NQ / 32, 256>>>(pred_logits);   // 8000 blocks, 32 queries each
    k_topk<<<BATCH, 256>>>(pred_boxes, target_sizes, out);
}

// round 4
// speedup vs baseline: 2.4797x; 2.4797x over previous
#include <cuda_runtime.h>
#include <cuda_bf16.h>
#include <float.h>

#define BATCH 256
#define NQ 1000
#define NC 80
#define TOPK 300
#define THRESH 0.05f

typedef unsigned long long u64;
typedef unsigned int u32;

__device__ u64 g_keys[BATCH * NQ];

// Order-preserving bijection float -> uint32 (monotone increasing)
__device__ __forceinline__ u32 fkey(float f) {
    u32 u = __float_as_uint(f);
    int  fl = ((int)u) >> 31;                 // 0 or 0xFFFFFFFF
    return u ^ ((u32)fl | 0x80000000u);       // pos: |0x8000..., neg: ~u
}
__device__ __forceinline__ float ikey(u32 k) {
    u32 u = (k & 0x80000000u) ? (k ^ 0x80000000u) : ~k;
    return __uint_as_float(u);
}

// ---------------------------------------------------------------------------
// Kernel 1: 256 threads stage 64 rows (21.5KB, rows padded to 21 float4),
// then 4 threads/row scan 5 float4 each (FSETP/FSEL, ascending class order =
// jax tie-break), 2-stage shfl pair reduction, lane q==0 writes the sort key:
//   key = [fkey(masked_score):32 | (1023-qi):10 | label:7]
// Sorting keys descending reproduces jax top_k order exactly.
// ---------------------------------------------------------------------------
#define RPB 64   // rows per block
#define PAD 21   // padded float4 per row

__global__ void __launch_bounds__(256) k_maxarg(const float* __restrict__ logits) {
    __shared__ float4 sm[RPB * PAD];
    const float4* in = reinterpret_cast<const float4*>(logits) + (size_t)blockIdx.x * (RPB * 20);
    int t = threadIdx.x;

    // Stage: 1280 float4, coalesced, MLP=5
    #pragma unroll
    for (int u = 0; u < 5; u++) {
        int g = u * 256 + t;
        int row = g / 20;
        int col = g - row * 20;
        sm[row * PAD + col] = in[g];
    }
    __syncthreads();

    int r = t >> 2, q = t & 3;           // 4 threads per row, q = quarter
    const float4* rp = &sm[r * PAD + q * 5];

    float v = -FLT_MAX; int c = 0;
    #pragma unroll
    for (int k = 0; k < 5; k++) {
        float4 x = rp[k];
        int base = q * 20 + k * 4;
        if (x.x > v) { v = x.x; c = base;     }
        if (x.y > v) { v = x.y; c = base + 1; }
        if (x.z > v) { v = x.z; c = base + 2; }
        if (x.w > v) { v = x.w; c = base + 3; }
    }
    #pragma unroll
    for (int off = 1; off <= 2; off <<= 1) {
        float v2 = __shfl_xor_sync(0xffffffffu, v, off);
        int   c2 = __shfl_xor_sync(0xffffffffu, c, off);
        if (v2 > v || (v2 == v && c2 < c)) { v = v2; c = c2; }
    }
    if (q == 0) {
        float s = 1.0f / (1.0f + expf(-v));
        float masked = (s > THRESH) ? s : -1.0f;
        int gq = blockIdx.x * RPB + r;
        int qi = gq % NQ;
        g_keys[gq] = ((u64)fkey(masked) << 17)
                   | ((u64)(1023 - qi) << 7)
                   | (u32)c;
    }
}

// ---------------------------------------------------------------------------
// Kernel 2: one batch per 512-thread block, 2 keys/thread in registers.
// Element i = warp*64 + r*32 + lane.
//   j < 32  : intra-warp shfl (39 phases, no smem, no barrier)
//   j == 32 : register swap within thread (6 phases, free)
//   j >= 64 : double-buffered smem exchange, ONE barrier per phase (10 phases)
// ---------------------------------------------------------------------------
__device__ __forceinline__ u64 shfl_xor_u64(u64 v, int m) {
    u32 lo = __shfl_xor_sync(0xffffffffu, (u32)v, m);
    u32 hi = __shfl_xor_sync(0xffffffffu, (u32)(v >> 32), m);
    return ((u64)hi << 32) | lo;
}

__global__ void __launch_bounds__(512) k_topk(const float* __restrict__ boxes,
                                              const float* __restrict__ tsizes,
                                              float* __restrict__ out) {
    __shared__ u64 sm[2][1024];
    int b = blockIdx.x;
    int t = threadIdx.x;
    int warp = t >> 5, lane = t & 31;
    int i0 = (warp << 6) | lane;          // element for r=0; r=1 is i0+32

    u64 v[2];
    #pragma unroll
    for (int r = 0; r < 2; r++) {
        int i = i0 + (r << 5);
        v[r] = (i < NQ) ? g_keys[b * NQ + i] : 0ULL;  // pads sort below real keys
    }

    int buf = 0;
    #pragma unroll 1
    for (int k = 2; k <= 1024; k <<= 1) {
        #pragma unroll 1
        for (int j = k >> 1; j > 0; j >>= 1) {
            if (j >= 64) {
                sm[buf][i0]      = v[0];
                sm[buf][i0 + 32] = v[1];
                __syncthreads();
                #pragma unroll
                for (int r = 0; r < 2; r++) {
                    int i = i0 + (r << 5);
                    u64 o = sm[buf][i ^ j];
                    bool keepmax = ((i & k) == 0) != ((i & j) != 0);
                    if (keepmax ? (o > v[r]) : (o < v[r])) v[r] = o;
                }
                buf ^= 1;
            } else if (j == 32) {
                bool desc = (i0 & k) == 0;          // k>=64: same for both regs
                u64 a = v[0], c2 = v[1];
                u64 mx = (a > c2) ? a : c2;
                u64 mn = (a > c2) ? c2 : a;
                v[0] = desc ? mx : mn;
                v[1] = desc ? mn : mx;
            } else {
                #pragma unroll
                for (int r = 0; r < 2; r++) {
                    int i = i0 + (r << 5);
                    u64 o = shfl_xor_u64(v[r], j);
                    bool keepmax = ((i & k) == 0) != ((i & j) != 0);
                    if (keepmax ? (o > v[r]) : (o < v[r])) v[r] = o;
                }
            }
        }
    }

    // Epilogue straight from registers (elements 0..299 live in warps 0..4)
    float img_h = tsizes[b * 2 + 0];
    float img_w = tsizes[b * 2 + 1];
    const float4* bx4 = reinterpret_cast<const float4*>(boxes) + (size_t)b * NQ;

    #pragma unroll
    for (int r = 0; r < 2; r++) {
        int i = i0 + (r << 5);
        if (i >= TOPK) continue;
        u64 key = v[r];
        float masked = ikey((u32)(key >> 17));
        int label = (int)(key & 127ULL);
        int qi = 1023 - (int)((key >> 7) & 1023ULL);
        bool valid = masked > THRESH;

        float4 bx = bx4[qi];
        float x0 = (bx.x - 0.5f * bx.z) * img_w;
        float y0 = (bx.y - 0.5f * bx.w) * img_h;
        float x1 = (bx.x + 0.5f * bx.z) * img_w;
        float y1 = (bx.y + 0.5f * bx.w) * img_h;

        int o = b * TOPK + i;
        out[o] = valid ? masked : 0.0f;
        out[BATCH * TOPK + o] = valid ? (float)label : -1.0f;
        float* ob = out + 2 * BATCH * TOPK + (size_t)o * 4;
        ob[0] = valid ? x0 : 0.0f;
        ob[1] = valid ? y0 : 0.0f;
        ob[2] = valid ? x1 : 0.0f;
        ob[3] = valid ? y1 : 0.0f;
    }
}

extern "C" void kernel_launch(void* const* d_in, const int* in_sizes, int n_in,
                              void* d_out, int out_size) {
    const float* pred_logits  = (const float*)d_in[0];
    const float* pred_boxes   = (const float*)d_in[1];
    const float* target_sizes = (const float*)d_in[2];
    float* out = (float*)d_out;

    k_maxarg<<<BATCH * NQ / RPB, 256>>>(pred_logits);   // 4000 blocks, 64 rows each
    k_topk<<<BATCH, 512>>>(pred_boxes, target_sizes, out);
}

// round 5
// speedup vs baseline: 3.5779x; 1.4429x over previous
#include <cuda_runtime.h>
#include <cuda_bf16.h>
#include <float.h>

#define BATCH 256
#define NQ 1000
#define NC 80
#define TOPK 300
#define THRESH 0.05f

typedef unsigned long long u64;
typedef unsigned int u32;

__device__ u64 g_keys[BATCH * NQ];

// Order-preserving bijection float -> uint32 (monotone increasing)
__device__ __forceinline__ u32 fkey(float f) {
    u32 u = __float_as_uint(f);
    int  fl = ((int)u) >> 31;
    return u ^ ((u32)fl | 0x80000000u);
}
__device__ __forceinline__ float ikey(u32 k) {
    u32 u = (k & 0x80000000u) ? (k ^ 0x80000000u) : ~k;
    return __uint_as_float(u);
}

// ---------------------------------------------------------------------------
// Kernel 1 (unchanged from R4 — measured ~14us, near DRAM roofline):
// 256 threads stage 64 rows (21.5KB, rows padded to 21 float4), then 4
// threads/row scan 5 float4 (ascending class order = jax argmax tie-break),
// 2-stage shfl pair reduce.  key = [fkey(masked):32 | (1023-qi):10 | label:7]
// ---------------------------------------------------------------------------
#define RPB 64
#define PAD 21

__global__ void __launch_bounds__(256) k_maxarg(const float* __restrict__ logits) {
    __shared__ float4 sm[RPB * PAD];
    const float4* in = reinterpret_cast<const float4*>(logits) + (size_t)blockIdx.x * (RPB * 20);
    int t = threadIdx.x;

    #pragma unroll
    for (int u = 0; u < 5; u++) {
        int g = u * 256 + t;
        int row = g / 20;
        int col = g - row * 20;
        sm[row * PAD + col] = in[g];
    }
    __syncthreads();

    int r = t >> 2, q = t & 3;
    const float4* rp = &sm[r * PAD + q * 5];

    float v = -FLT_MAX; int c = 0;
    #pragma unroll
    for (int k = 0; k < 5; k++) {
        float4 x = rp[k];
        int base = q * 20 + k * 4;
        if (x.x > v) { v = x.x; c = base;     }
        if (x.y > v) { v = x.y; c = base + 1; }
        if (x.z > v) { v = x.z; c = base + 2; }
        if (x.w > v) { v = x.w; c = base + 3; }
    }
    #pragma unroll
    for (int off = 1; off <= 2; off <<= 1) {
        float v2 = __shfl_xor_sync(0xffffffffu, v, off);
        int   c2 = __shfl_xor_sync(0xffffffffu, c, off);
        if (v2 > v || (v2 == v && c2 < c)) { v = v2; c = c2; }
    }
    if (q == 0) {
        float s = 1.0f / (1.0f + expf(-v));
        float masked = (s > THRESH) ? s : -1.0f;
        int gq = blockIdx.x * RPB + r;
        int qi = gq % NQ;
        g_keys[gq] = ((u64)fkey(masked) << 17)
                   | ((u64)(1023 - qi) << 7)
                   | (u32)c;
    }
}

// ---------------------------------------------------------------------------
// Kernel 2: bitonic sort of 1024 keys, FULLY UNROLLED phases (K, J are
// template constants -> all masks/widths constant-folded). 512 threads,
// 2 keys/thread; element i = warp*64 + r*32 + lane.
//   40 shfl phases (j<=16), 5 register phases (j=32),
//   10 smem phases (j>=64) with static double-buffering, ONE barrier each.
// ---------------------------------------------------------------------------
__device__ __forceinline__ u64 shfl_xor_u64(u64 v, int m) {
    u32 lo = __shfl_xor_sync(0xffffffffu, (u32)v, m);
    u32 hi = __shfl_xor_sync(0xffffffffu, (u32)(v >> 32), m);
    return ((u64)hi << 32) | lo;
}

template<int K, int J>
__device__ __forceinline__ void phase_shfl(u64 v[2], int lane, int warp) {
    #pragma unroll
    for (int r = 0; r < 2; r++) {
        int i = (warp << 6) | (r << 5) | lane;
        u64 o = shfl_xor_u64(v[r], J);
        bool keep_hi = ((i & K) == 0) != ((lane & J) != 0);
        bool ogt = o > v[r];
        v[r] = (keep_hi == ogt) ? o : v[r];
    }
}

template<int K>
__device__ __forceinline__ void phase_reg32(u64 v[2], int warp) {
    bool desc = (((warp << 6)) & K) == 0;   // K>=64: bit5 (=r) never in K
    u64 a = v[0], b = v[1];
    bool agt = a > b;
    u64 mx = agt ? a : b;
    u64 mn = agt ? b : a;
    v[0] = desc ? mx : mn;
    v[1] = desc ? mn : mx;
}

template<int K, int J, int BUF>
__device__ __forceinline__ void phase_smem(u64 v[2], u64 sm[2][1024], int i0) {
    sm[BUF][i0]      = v[0];
    sm[BUF][i0 + 32] = v[1];
    __syncthreads();
    #pragma unroll
    for (int r = 0; r < 2; r++) {
        int i = i0 + (r << 5);
        u64 o = sm[BUF][i ^ J];
        bool keep_hi = ((i & K) == 0) != ((i & J) != 0);
        bool ogt = o > v[r];
        v[r] = (keep_hi == ogt) ? o : v[r];
    }
}

// all shfl phases for one k (j = 16..1), used for K >= 32
template<int K>
__device__ __forceinline__ void phases_shfl_16_1(u64 v[2], int lane, int warp) {
    phase_shfl<K, 16>(v, lane, warp);
    phase_shfl<K,  8>(v, lane, warp);
    phase_shfl<K,  4>(v, lane, warp);
    phase_shfl<K,  2>(v, lane, warp);
    phase_shfl<K,  1>(v, lane, warp);
}

__global__ void __launch_bounds__(512) k_topk(const float* __restrict__ boxes,
                                              const float* __restrict__ tsizes,
                                              float* __restrict__ out) {
    __shared__ u64 sm[2][1024];
    int b = blockIdx.x;
    int t = threadIdx.x;
    int warp = t >> 5, lane = t & 31;
    int i0 = (warp << 6) | lane;

    u64 v[2];
    #pragma unroll
    for (int r = 0; r < 2; r++) {
        int i = i0 + (r << 5);
        v[r] = (i < NQ) ? g_keys[b * NQ + i] : 0ULL;
    }

    // k=2..16
    phase_shfl<2, 1>(v, lane, warp);
    phase_shfl<4, 2>(v, lane, warp); phase_shfl<4, 1>(v, lane, warp);
    phase_shfl<8, 4>(v, lane, warp); phase_shfl<8, 2>(v, lane, warp); phase_shfl<8, 1>(v, lane, warp);
    phase_shfl<16, 8>(v, lane, warp); phase_shfl<16, 4>(v, lane, warp);
    phase_shfl<16, 2>(v, lane, warp); phase_shfl<16, 1>(v, lane, warp);
    // k=32
    phases_shfl_16_1<32>(v, lane, warp);
    // k=64
    phase_reg32<64>(v, warp);
    phases_shfl_16_1<64>(v, lane, warp);
    // k=128
    phase_smem<128, 64, 0>(v, sm, i0);
    phase_reg32<128>(v, warp);
    phases_shfl_16_1<128>(v, lane, warp);
    // k=256
    phase_smem<256, 128, 1>(v, sm, i0);
    phase_smem<256,  64, 0>(v, sm, i0);
    phase_reg32<256>(v, warp);
    phases_shfl_16_1<256>(v, lane, warp);
    // k=512
    phase_smem<512, 256, 1>(v, sm, i0);
    phase_smem<512, 128, 0>(v, sm, i0);
    phase_smem<512,  64, 1>(v, sm, i0);
    phase_reg32<512>(v, warp);
    phases_shfl_16_1<512>(v, lane, warp);
    // k=1024
    phase_smem<1024, 512, 0>(v, sm, i0);
    phase_smem<1024, 256, 1>(v, sm, i0);
    phase_smem<1024, 128, 0>(v, sm, i0);
    phase_smem<1024,  64, 1>(v, sm, i0);
    phase_reg32<1024>(v, warp);
    phases_shfl_16_1<1024>(v, lane, warp);

    // Epilogue straight from registers (elements 0..299 live in warps 0..4)
    float img_h = tsizes[b * 2 + 0];
    float img_w = tsizes[b * 2 + 1];
    const float4* bx4 = reinterpret_cast<const float4*>(boxes) + (size_t)b * NQ;

    #pragma unroll
    for (int r = 0; r < 2; r++) {
        int i = i0 + (r << 5);
        if (i >= TOPK) continue;
        u64 key = v[r];
        float masked = ikey((u32)(key >> 17));
        int label = (int)(key & 127ULL);
        int qi = 1023 - (int)((key >> 7) & 1023ULL);
        bool valid = masked > THRESH;

        float4 bx = bx4[qi];
        float x0 = (bx.x - 0.5f * bx.z) * img_w;
        float y0 = (bx.y - 0.5f * bx.w) * img_h;
        float x1 = (bx.x + 0.5f * bx.z) * img_w;
        float y1 = (bx.y + 0.5f * bx.w) * img_h;

        int o = b * TOPK + i;
        out[o] = valid ? masked : 0.0f;
        out[BATCH * TOPK + o] = valid ? (float)label : -1.0f;
        float* ob = out + 2 * BATCH * TOPK + (size_t)o * 4;
        ob[0] = valid ? x0 : 0.0f;
        ob[1] = valid ? y0 : 0.0f;
        ob[2] = valid ? x1 : 0.0f;
        ob[3] = valid ? y1 : 0.0f;
    }
}

extern "C" void kernel_launch(void* const* d_in, const int* in_sizes, int n_in,
                              void* d_out, int out_size) {
    const float* pred_logits  = (const float*)d_in[0];
    const float* pred_boxes   = (const float*)d_in[1];
    const float* target_sizes = (const float*)d_in[2];
    float* out = (float*)d_out;

    k_maxarg<<<BATCH * NQ / RPB, 256>>>(pred_logits);
    k_topk<<<BATCH, 512>>>(pred_boxes, target_sizes, out);
}